// round 1
// baseline (speedup 1.0000x reference)
#include <cuda_runtime.h>
#include <cuda_bf16.h>
#include <math.h>

// Problem constants (B=2, T=2048)
#define N_TOK 4096
#define CDIM  2048
#define EXPN  8
#define IDIM  5632

// GEMM tiling
#define BM 64
#define BN 64
#define BK 16

// total tiles <= N_TOK*2/BM + EXPN = 128 + 8 = 136 (fixed grid for graph capture)
#define MAX_TILES 136
#define ROWS_PAD  (MAX_TILES * BM)   // 8704

// ---------------- device scratch (static, no allocation) ----------------
__device__ int   g_row_token[ROWS_PAD];
__device__ float g_row_w[ROWS_PAD];
__device__ int   g_tile_expert[MAX_TILES];
__device__ int   g_counts[EXPN];
__device__ int   g_cursor[EXPN];
__device__ int   g_off[EXPN];
__device__ int   g_tk_idx[N_TOK * 2];
__device__ float g_tk_w[N_TOK * 2];
__device__ float g_h[(size_t)ROWS_PAD * IDIM];   // ~187 MB intermediate

// ---------------- reset ----------------
__global__ void reset_kernel() {
    int i = blockIdx.x * blockDim.x + threadIdx.x;
    if (i < ROWS_PAD) { g_row_token[i] = -1; g_row_w[i] = 0.f; }
    if (i < MAX_TILES) g_tile_expert[i] = -1;
    if (i < EXPN) { g_counts[i] = 0; g_cursor[i] = 0; }
}

// ---------------- router: logits, top-2, softmax ----------------
__global__ void __launch_bounds__(256) router_kernel(
        const float* __restrict__ x, const float* __restrict__ gw) {
    int t = blockIdx.x;
    const float* xr = x + (size_t)t * CDIM;
    float acc[EXPN] = {0.f, 0.f, 0.f, 0.f, 0.f, 0.f, 0.f, 0.f};
    for (int k = threadIdx.x; k < CDIM; k += 256) {
        float xv = xr[k];
#pragma unroll
        for (int e = 0; e < EXPN; e++) acc[e] = fmaf(xv, gw[e * CDIM + k], acc[e]);
    }
#pragma unroll
    for (int off = 16; off > 0; off >>= 1)
#pragma unroll
        for (int e = 0; e < EXPN; e++)
            acc[e] += __shfl_down_sync(0xffffffffu, acc[e], off);

    __shared__ float sw[8][EXPN];
    __shared__ float slog[EXPN];
    int wid = threadIdx.x >> 5, lane = threadIdx.x & 31;
    if (lane == 0) {
#pragma unroll
        for (int e = 0; e < EXPN; e++) sw[wid][e] = acc[e];
    }
    __syncthreads();
    if (threadIdx.x < EXPN) {
        float s = 0.f;
#pragma unroll
        for (int w = 0; w < 8; w++) s += sw[w][threadIdx.x];  // fixed order: deterministic
        slog[threadIdx.x] = s;
    }
    __syncthreads();
    if (threadIdx.x == 0) {
        int i0 = 0;
        for (int e = 1; e < EXPN; e++) if (slog[e] > slog[i0]) i0 = e;
        int i1 = (i0 == 0) ? 1 : 0;
        for (int e = 0; e < EXPN; e++)
            if (e != i0 && slog[e] > slog[i1]) i1 = e;
        float v0 = slog[i0], v1 = slog[i1];
        float e1 = expf(v1 - v0);
        float inv = 1.f / (1.f + e1);
        g_tk_idx[2 * t + 0] = i0;  g_tk_idx[2 * t + 1] = i1;
        g_tk_w[2 * t + 0] = inv;   g_tk_w[2 * t + 1] = e1 * inv;
        atomicAdd(&g_counts[i0], 1);
        atomicAdd(&g_counts[i1], 1);
    }
}

// ---------------- offsets (1 thread, tiny) ----------------
__global__ void offsets_kernel() {
    if (blockIdx.x == 0 && threadIdx.x == 0) {
        int tileIdx = 0;
        for (int e = 0; e < EXPN; e++) {
            g_off[e] = tileIdx * BM;
            int nt = (g_counts[e] + BM - 1) / BM;
            for (int j = 0; j < nt; j++) g_tile_expert[tileIdx++] = e;
        }
    }
}

// ---------------- fill per-expert row lists ----------------
__global__ void fill_kernel() {
    int t = blockIdx.x * blockDim.x + threadIdx.x;
    if (t >= N_TOK) return;
#pragma unroll
    for (int s = 0; s < 2; s++) {
        int e = g_tk_idx[2 * t + s];
        float w = g_tk_w[2 * t + s];
        int pos = atomicAdd(&g_cursor[e], 1);
        int r = g_off[e] + pos;
        g_row_token[r] = t;
        g_row_w[r] = w;
    }
}

// ---------------- zero output ----------------
__global__ void zero_out_kernel(float* __restrict__ out, int n) {
    int i = blockIdx.x * blockDim.x + threadIdx.x;
    if (i < n) out[i] = 0.f;
}

// ---------------- GEMM1: H = silu(X @ fc1_e^T) * (X @ fc2_e^T) * w_row ----------------
__global__ void __launch_bounds__(256) gemm1_kernel(
        const float* __restrict__ x,
        const float* __restrict__ fc1,
        const float* __restrict__ fc2) {
    const int tile = blockIdx.x;
    const int e = g_tile_expert[tile];
    if (e < 0) return;
    const int n0 = blockIdx.y * BN;   // over IDIM

    __shared__ float sA[BK][BM];
    __shared__ float sB1[BK][BN];
    __shared__ float sB2[BK][BN];

    const int tid = threadIdx.x;
    const int lr = tid >> 2;              // 0..63
    const int lk = (tid & 3) << 2;        // 0,4,8,12
    const int tr = (tid >> 4) << 2;       // 0..60 step 4 (M)
    const int tc = (tid & 15) << 2;       // 0..60 step 4 (N)

    const int row0 = tile * BM;
    int tok = g_row_token[row0 + lr];
    const float* arow = x + (size_t)(tok < 0 ? 0 : tok) * CDIM;
    const size_t wb = (size_t)e * IDIM * CDIM;
    const float* b1row = fc1 + wb + (size_t)(n0 + lr) * CDIM;
    const float* b2row = fc2 + wb + (size_t)(n0 + lr) * CDIM;

    float acc1[4][4] = {};
    float acc2[4][4] = {};

    for (int k0 = 0; k0 < CDIM; k0 += BK) {
        float4 a4  = *(const float4*)(arow  + k0 + lk);
        float4 b14 = *(const float4*)(b1row + k0 + lk);
        float4 b24 = *(const float4*)(b2row + k0 + lk);
        __syncthreads();
        sA [lk + 0][lr] = a4.x;  sA [lk + 1][lr] = a4.y;
        sA [lk + 2][lr] = a4.z;  sA [lk + 3][lr] = a4.w;
        sB1[lk + 0][lr] = b14.x; sB1[lk + 1][lr] = b14.y;
        sB1[lk + 2][lr] = b14.z; sB1[lk + 3][lr] = b14.w;
        sB2[lk + 0][lr] = b24.x; sB2[lk + 1][lr] = b24.y;
        sB2[lk + 2][lr] = b24.z; sB2[lk + 3][lr] = b24.w;
        __syncthreads();
#pragma unroll
        for (int kk = 0; kk < BK; kk++) {
            float a[4], b1[4], b2[4];
#pragma unroll
            for (int i = 0; i < 4; i++) a[i] = sA[kk][tr + i];
#pragma unroll
            for (int j = 0; j < 4; j++) { b1[j] = sB1[kk][tc + j]; b2[j] = sB2[kk][tc + j]; }
#pragma unroll
            for (int i = 0; i < 4; i++)
#pragma unroll
                for (int j = 0; j < 4; j++) {
                    acc1[i][j] = fmaf(a[i], b1[j], acc1[i][j]);
                    acc2[i][j] = fmaf(a[i], b2[j], acc2[i][j]);
                }
        }
    }

#pragma unroll
    for (int i = 0; i < 4; i++) {
        float w = g_row_w[row0 + tr + i];
        float* hrow = g_h + (size_t)(row0 + tr + i) * IDIM + n0 + tc;
#pragma unroll
        for (int j = 0; j < 4; j++) {
            float s1 = acc1[i][j];
            float s2 = acc2[i][j];
            float silu = s1 / (1.f + expf(-s1));
            hrow[j] = silu * s2 * w;
        }
    }
}

// ---------------- GEMM2: out[token] += H_row @ proj_e^T ----------------
__global__ void __launch_bounds__(256) gemm2_kernel(
        const float* __restrict__ proj, float* __restrict__ out) {
    const int tile = blockIdx.x;
    const int e = g_tile_expert[tile];
    if (e < 0) return;
    const int n0 = blockIdx.y * BN;   // over CDIM

    __shared__ float sA[BK][BM];
    __shared__ float sB[BK][BN];

    const int tid = threadIdx.x;
    const int lr = tid >> 2;
    const int lk = (tid & 3) << 2;
    const int tr = (tid >> 4) << 2;
    const int tc = (tid & 15) << 2;

    const int row0 = tile * BM;
    const float* arow = g_h + (size_t)(row0 + lr) * IDIM;
    const float* brow = proj + (size_t)e * CDIM * IDIM + (size_t)(n0 + lr) * IDIM;

    float acc[4][4] = {};

    for (int k0 = 0; k0 < IDIM; k0 += BK) {
        float4 a4 = *(const float4*)(arow + k0 + lk);
        float4 b4 = *(const float4*)(brow + k0 + lk);
        __syncthreads();
        sA[lk + 0][lr] = a4.x; sA[lk + 1][lr] = a4.y;
        sA[lk + 2][lr] = a4.z; sA[lk + 3][lr] = a4.w;
        sB[lk + 0][lr] = b4.x; sB[lk + 1][lr] = b4.y;
        sB[lk + 2][lr] = b4.z; sB[lk + 3][lr] = b4.w;
        __syncthreads();
#pragma unroll
        for (int kk = 0; kk < BK; kk++) {
            float a[4], b[4];
#pragma unroll
            for (int i = 0; i < 4; i++) a[i] = sA[kk][tr + i];
#pragma unroll
            for (int j = 0; j < 4; j++) b[j] = sB[kk][tc + j];
#pragma unroll
            for (int i = 0; i < 4; i++)
#pragma unroll
                for (int j = 0; j < 4; j++)
                    acc[i][j] = fmaf(a[i], b[j], acc[i][j]);
        }
    }

#pragma unroll
    for (int i = 0; i < 4; i++) {
        int tok = g_row_token[row0 + tr + i];
        if (tok < 0) continue;
        float* orow = out + (size_t)tok * CDIM + n0 + tc;
#pragma unroll
        for (int j = 0; j < 4; j++)
            atomicAdd(orow + j, acc[i][j]);   // exactly 2 adds/elem on 0-base: deterministic
    }
}

// ---------------- launch ----------------
extern "C" void kernel_launch(void* const* d_in, const int* in_sizes, int n_in,
                              void* d_out, int out_size) {
    const float* x    = (const float*)d_in[0];
    const float* gate = (const float*)d_in[1];
    const float* fc1  = (const float*)d_in[2];
    const float* fc2  = (const float*)d_in[3];
    const float* proj = (const float*)d_in[4];
    float* out = (float*)d_out;

    reset_kernel<<<(ROWS_PAD + 255) / 256, 256>>>();
    router_kernel<<<N_TOK, 256>>>(x, gate);
    offsets_kernel<<<1, 32>>>();
    fill_kernel<<<(N_TOK + 255) / 256, 256>>>();
    zero_out_kernel<<<(out_size + 1023) / 1024, 1024>>>(out, out_size);
    gemm1_kernel<<<dim3(MAX_TILES, IDIM / BN), 256>>>(x, fc1, fc2);
    gemm2_kernel<<<dim3(MAX_TILES, CDIM / BN), 256>>>(proj, out);
}

// round 3
// speedup vs baseline: 3.5762x; 3.5762x over previous
#include <cuda_runtime.h>
#include <cuda_bf16.h>
#include <math.h>
#include <stdint.h>

// Problem constants (B=2, T=2048)
#define N_TOK 4096
#define CDIM  2048
#define EXPN  8
#define IDIM  5632

#define BMROWS 128                        // bucket / M tile
#define MAX_TILES 72                      // 8192/128 + 8
#define ROWS_PAD (MAX_TILES * BMROWS)     // 9216

#define BK 32
#define LDP 36                            // padded row stride in floats
#define STAGES 3

// GEMM1 stage layout (floats): A 128*36=4608 | B1 64*36=2304 | B2 2304 => 9216 floats
#define G1_STAGE_F 9216
#define G1_B1_F    4608
#define G1_B2_F    6912
// GEMM2 stage layout: A 4608 | B 128*36=4608 => 9216 floats
#define G2_STAGE_F 9216
#define G2_B_F     4608
#define DSMEM_BYTES (STAGES * 9216 * 4)   // 110592

// ---------------- device scratch ----------------
__device__ int   g_row_token[ROWS_PAD];
__device__ float g_row_w[ROWS_PAD];
__device__ int   g_tile_expert[MAX_TILES];
__device__ int   g_counts[EXPN];
__device__ int   g_cursor[EXPN];
__device__ int   g_off[EXPN];
__device__ int   g_tk_idx[N_TOK * 2];
__device__ float g_tk_w[N_TOK * 2];
__device__ float g_h[(size_t)ROWS_PAD * IDIM];   // ~208 MB intermediate

// ---------------- helpers ----------------
__device__ __forceinline__ uint32_t smem_u32(const void* p) {
    uint32_t a;
    asm("{ .reg .u64 t; cvta.to.shared.u64 t, %1; cvt.u32.u64 %0, t; }" : "=r"(a) : "l"(p));
    return a;
}
__device__ __forceinline__ uint32_t cvt_tf32(uint32_t raw) {
    uint32_t r;
    asm("cvt.rna.tf32.f32 %0, %1;" : "=r"(r) : "f"(__uint_as_float(raw)));
    return r;
}
__device__ __forceinline__ void cp16(uint32_t dst, const void* src) {
    asm volatile("cp.async.cg.shared.global [%0], [%1], 16;" :: "r"(dst), "l"(src) : "memory");
}
__device__ __forceinline__ void cp_commit() {
    asm volatile("cp.async.commit_group;" ::: "memory");
}
__device__ __forceinline__ void cp_wait1() {
    asm volatile("cp.async.wait_group 1;" ::: "memory");
}
__device__ __forceinline__ void cp_wait0() {
    asm volatile("cp.async.wait_group 0;" ::: "memory");
}
#define MMA_TF32(d, a, b) asm volatile( \
    "mma.sync.aligned.m16n8k8.row.col.f32.tf32.tf32.f32 " \
    "{%0,%1,%2,%3},{%4,%5,%6,%7},{%8,%9},{%0,%1,%2,%3};" \
    : "+f"((d)[0]), "+f"((d)[1]), "+f"((d)[2]), "+f"((d)[3]) \
    : "r"((a)[0]), "r"((a)[1]), "r"((a)[2]), "r"((a)[3]), \
      "r"((b)[0]), "r"((b)[1]))

// ---------------- reset ----------------
__global__ void reset_kernel() {
    int i = blockIdx.x * blockDim.x + threadIdx.x;
    if (i < ROWS_PAD) { g_row_token[i] = 0; g_row_w[i] = 0.f; }
    if (i < MAX_TILES) g_tile_expert[i] = -1;
    if (i < EXPN) { g_counts[i] = 0; g_cursor[i] = 0; }
}

// ---------------- router ----------------
__global__ void __launch_bounds__(256) router_kernel(
        const float* __restrict__ x, const float* __restrict__ gw) {
    int t = blockIdx.x;
    const float* xr = x + (size_t)t * CDIM;
    float acc[EXPN] = {};
    for (int k = threadIdx.x; k < CDIM; k += 256) {
        float xv = xr[k];
#pragma unroll
        for (int e = 0; e < EXPN; e++) acc[e] = fmaf(xv, gw[e * CDIM + k], acc[e]);
    }
#pragma unroll
    for (int off = 16; off > 0; off >>= 1)
#pragma unroll
        for (int e = 0; e < EXPN; e++)
            acc[e] += __shfl_down_sync(0xffffffffu, acc[e], off);

    __shared__ float sw[8][EXPN];
    __shared__ float slog[EXPN];
    int wid = threadIdx.x >> 5, lane = threadIdx.x & 31;
    if (lane == 0)
#pragma unroll
        for (int e = 0; e < EXPN; e++) sw[wid][e] = acc[e];
    __syncthreads();
    if (threadIdx.x < EXPN) {
        float s = 0.f;
#pragma unroll
        for (int w = 0; w < 8; w++) s += sw[w][threadIdx.x];
        slog[threadIdx.x] = s;
    }
    __syncthreads();
    if (threadIdx.x == 0) {
        int i0 = 0;
        for (int e = 1; e < EXPN; e++) if (slog[e] > slog[i0]) i0 = e;
        int i1 = (i0 == 0) ? 1 : 0;
        for (int e = 0; e < EXPN; e++)
            if (e != i0 && slog[e] > slog[i1]) i1 = e;
        float e1 = expf(slog[i1] - slog[i0]);
        float inv = 1.f / (1.f + e1);
        g_tk_idx[2 * t + 0] = i0;  g_tk_idx[2 * t + 1] = i1;
        g_tk_w[2 * t + 0] = inv;   g_tk_w[2 * t + 1] = e1 * inv;
        atomicAdd(&g_counts[i0], 1);
        atomicAdd(&g_counts[i1], 1);
    }
}

// ---------------- offsets ----------------
__global__ void offsets_kernel() {
    if (blockIdx.x == 0 && threadIdx.x == 0) {
        int tileIdx = 0;
        for (int e = 0; e < EXPN; e++) {
            g_off[e] = tileIdx * BMROWS;
            int nt = (g_counts[e] + BMROWS - 1) / BMROWS;
            for (int j = 0; j < nt; j++) g_tile_expert[tileIdx++] = e;
        }
    }
}

// ---------------- fill ----------------
__global__ void fill_kernel() {
    int t = blockIdx.x * blockDim.x + threadIdx.x;
    if (t >= N_TOK) return;
#pragma unroll
    for (int s = 0; s < 2; s++) {
        int e = g_tk_idx[2 * t + s];
        float w = g_tk_w[2 * t + s];
        int pos = atomicAdd(&g_cursor[e], 1);
        int r = g_off[e] + pos;
        g_row_token[r] = t;
        g_row_w[r] = w;
    }
}

// ---------------- zero output ----------------
__global__ void zero_out_kernel(float* __restrict__ out, int n) {
    int i = blockIdx.x * blockDim.x + threadIdx.x;
    if (i < n) out[i] = 0.f;
}

// =========== GEMM1: H = silu(X@fc1^T) * (X@fc2^T) * w  (mma.sync tf32) ===========
// CTA tile 128(M) x 64(N over IDIM), warp tile 32x32, dual accumulators.
__global__ void __launch_bounds__(256) gemm1_kernel(
        const float* __restrict__ x,
        const float* __restrict__ fc1,
        const float* __restrict__ fc2) {
    extern __shared__ float sm[];
    __shared__ int s_tok[BMROWS];
    __shared__ float s_w[BMROWS];

    const int tile = blockIdx.x;
    const int e = g_tile_expert[tile];
    if (e < 0) return;
    const int n0 = blockIdx.y * 64;
    const int tid = threadIdx.x;
    const int wid = tid >> 5, lane = tid & 31;
    const int wm = wid >> 1, wn = wid & 1;
    const uint32_t dsm_u = smem_u32(sm);

    if (tid < BMROWS) {
        s_tok[tid] = g_row_token[tile * BMROWS + tid];
        s_w[tid]   = g_row_w[tile * BMROWS + tid];
    }
    __syncthreads();

    const size_t wb = (size_t)e * IDIM * CDIM;
    const float* b1base = fc1 + wb + (size_t)n0 * CDIM;
    const float* b2base = fc2 + wb + (size_t)n0 * CDIM;

    float acc1[2][4][4] = {};
    float acc2[2][4][4] = {};

    const int NCH = CDIM / BK;  // 64

    // ---- async stage issue ----
    auto issue = [&](int c) {
        const int st = c % STAGES;
        const int k0 = c * BK;
        const uint32_t base = dsm_u + (uint32_t)st * (G1_STAGE_F * 4);
#pragma unroll
        for (int j = 0; j < 4; j++) {           // A: 128 x 32
            int idx = (j << 8) + tid;
            int row = idx >> 3, c4 = (idx & 7) << 2;
            cp16(base + (uint32_t)(row * LDP + c4) * 4,
                 x + (size_t)s_tok[row] * CDIM + k0 + c4);
        }
#pragma unroll
        for (int j = 0; j < 2; j++) {           // B1/B2: 64 x 32 each
            int idx = (j << 8) + tid;
            int row = idx >> 3, c4 = (idx & 7) << 2;
            size_t so = (size_t)row * CDIM + k0 + c4;
            uint32_t off = (uint32_t)(row * LDP + c4) * 4;
            cp16(base + G1_B1_F * 4 + off, b1base + so);
            cp16(base + G1_B2_F * 4 + off, b2base + so);
        }
        cp_commit();
    };

    issue(0);
    issue(1);

    for (int c = 0; c < NCH; c++) {
        if (c + 1 < NCH) cp_wait1(); else cp_wait0();
        __syncthreads();
        if (c + 2 < NCH) issue(c + 2);

        const uint32_t* As = (const uint32_t*)sm + (c % STAGES) * G1_STAGE_F;
        const uint32_t* B1s = As + G1_B1_F;
        const uint32_t* B2s = As + G1_B2_F;
        const int r4 = lane >> 2, cl = lane & 3;
#pragma unroll
        for (int kk = 0; kk < 4; kk++) {
            const int k8 = kk << 3;
            uint32_t a[2][4];
#pragma unroll
            for (int mt = 0; mt < 2; mt++) {
                int r = wm * 32 + mt * 16 + r4;
                a[mt][0] = cvt_tf32(As[r * LDP + k8 + cl]);
                a[mt][1] = cvt_tf32(As[(r + 8) * LDP + k8 + cl]);
                a[mt][2] = cvt_tf32(As[r * LDP + k8 + cl + 4]);
                a[mt][3] = cvt_tf32(As[(r + 8) * LDP + k8 + cl + 4]);
            }
#pragma unroll
            for (int nt = 0; nt < 4; nt++) {
                int n = wn * 32 + nt * 8 + r4;
                uint32_t b1[2], b2[2];
                b1[0] = cvt_tf32(B1s[n * LDP + k8 + cl]);
                b1[1] = cvt_tf32(B1s[n * LDP + k8 + cl + 4]);
                b2[0] = cvt_tf32(B2s[n * LDP + k8 + cl]);
                b2[1] = cvt_tf32(B2s[n * LDP + k8 + cl + 4]);
#pragma unroll
                for (int mt = 0; mt < 2; mt++) {
                    MMA_TF32(acc1[mt][nt], a[mt], b1);
                    MMA_TF32(acc2[mt][nt], a[mt], b2);
                }
            }
        }
        __syncthreads();
    }

    // ---- epilogue: silu(acc1)*acc2*w -> g_h ----
    const int r4 = lane >> 2, c2 = (lane & 3) << 1;
#pragma unroll
    for (int mt = 0; mt < 2; mt++) {
#pragma unroll
        for (int hh = 0; hh < 2; hh++) {
            int lrow = wm * 32 + mt * 16 + r4 + 8 * hh;
            int grow = tile * BMROWS + lrow;
            float w = s_w[lrow];
            float* hp = g_h + (size_t)grow * IDIM + n0 + wn * 32 + c2;
#pragma unroll
            for (int nt = 0; nt < 4; nt++) {
                float a0 = acc1[mt][nt][2 * hh + 0];
                float a1 = acc1[mt][nt][2 * hh + 1];
                float b0 = acc2[mt][nt][2 * hh + 0];
                float b1 = acc2[mt][nt][2 * hh + 1];
                float2 o;
                o.x = w * b0 * (a0 / (1.f + expf(-a0)));
                o.y = w * b1 * (a1 / (1.f + expf(-a1)));
                *(float2*)(hp + nt * 8) = o;
            }
        }
    }
}

// =========== GEMM2: out[token] += H @ proj^T  (mma.sync tf32) ===========
// CTA tile 128(M) x 128(N over CDIM), warp tile 32x64.
__global__ void __launch_bounds__(256) gemm2_kernel(
        const float* __restrict__ proj, float* __restrict__ out) {
    extern __shared__ float sm[];
    __shared__ int s_tok[BMROWS];

    const int tile = blockIdx.x;
    const int e = g_tile_expert[tile];
    if (e < 0) return;
    const int n0 = blockIdx.y * 128;
    const int tid = threadIdx.x;
    const int wid = tid >> 5, lane = tid & 31;
    const int wm = wid >> 1, wn = wid & 1;
    const uint32_t dsm_u = smem_u32(sm);

    if (tid < BMROWS) s_tok[tid] = g_row_token[tile * BMROWS + tid];
    __syncthreads();

    const float* abase = g_h + (size_t)(tile * BMROWS) * IDIM;
    const float* bbase = proj + (size_t)e * CDIM * IDIM + (size_t)n0 * IDIM;

    float acc[2][8][4] = {};

    const int NCH = IDIM / BK;  // 176

    auto issue = [&](int c) {
        const int st = c % STAGES;
        const int k0 = c * BK;
        const uint32_t base = dsm_u + (uint32_t)st * (G2_STAGE_F * 4);
#pragma unroll
        for (int j = 0; j < 4; j++) {           // A: 128 x 32 from g_h
            int idx = (j << 8) + tid;
            int row = idx >> 3, c4 = (idx & 7) << 2;
            cp16(base + (uint32_t)(row * LDP + c4) * 4,
                 abase + (size_t)row * IDIM + k0 + c4);
        }
#pragma unroll
        for (int j = 0; j < 4; j++) {           // B: 128 x 32 from proj
            int idx = (j << 8) + tid;
            int row = idx >> 3, c4 = (idx & 7) << 2;
            cp16(base + (uint32_t)(G2_B_F + row * LDP + c4) * 4,
                 bbase + (size_t)row * IDIM + k0 + c4);
        }
        cp_commit();
    };

    issue(0);
    issue(1);

    for (int c = 0; c < NCH; c++) {
        if (c + 1 < NCH) cp_wait1(); else cp_wait0();
        __syncthreads();
        if (c + 2 < NCH) issue(c + 2);

        const uint32_t* As = (const uint32_t*)sm + (c % STAGES) * G2_STAGE_F;
        const uint32_t* Bs = As + G2_B_F;
        const int r4 = lane >> 2, cl = lane & 3;
#pragma unroll
        for (int kk = 0; kk < 4; kk++) {
            const int k8 = kk << 3;
            uint32_t a[2][4];
#pragma unroll
            for (int mt = 0; mt < 2; mt++) {
                int r = wm * 32 + mt * 16 + r4;
                a[mt][0] = cvt_tf32(As[r * LDP + k8 + cl]);
                a[mt][1] = cvt_tf32(As[(r + 8) * LDP + k8 + cl]);
                a[mt][2] = cvt_tf32(As[r * LDP + k8 + cl + 4]);
                a[mt][3] = cvt_tf32(As[(r + 8) * LDP + k8 + cl + 4]);
            }
#pragma unroll
            for (int nt = 0; nt < 8; nt++) {
                int n = wn * 64 + nt * 8 + r4;
                uint32_t b[2];
                b[0] = cvt_tf32(Bs[n * LDP + k8 + cl]);
                b[1] = cvt_tf32(Bs[n * LDP + k8 + cl + 4]);
#pragma unroll
                for (int mt = 0; mt < 2; mt++)
                    MMA_TF32(acc[mt][nt], a[mt], b);
            }
        }
        __syncthreads();
    }

    // ---- epilogue: atomic scatter-add to out (2 real adds/elem on zero base) ----
    const int r4 = lane >> 2, c2 = (lane & 3) << 1;
#pragma unroll
    for (int mt = 0; mt < 2; mt++) {
#pragma unroll
        for (int hh = 0; hh < 2; hh++) {
            int lrow = wm * 32 + mt * 16 + r4 + 8 * hh;
            int tok = s_tok[lrow];
            float* op = out + (size_t)tok * CDIM + n0 + wn * 64 + c2;
#pragma unroll
            for (int nt = 0; nt < 8; nt++) {
                atomicAdd(op + nt * 8 + 0, acc[mt][nt][2 * hh + 0]);
                atomicAdd(op + nt * 8 + 1, acc[mt][nt][2 * hh + 1]);
            }
        }
    }
}

// ---------------- launch ----------------
extern "C" void kernel_launch(void* const* d_in, const int* in_sizes, int n_in,
                              void* d_out, int out_size) {
    const float* x    = (const float*)d_in[0];
    const float* gate = (const float*)d_in[1];
    const float* fc1  = (const float*)d_in[2];
    const float* fc2  = (const float*)d_in[3];
    const float* proj = (const float*)d_in[4];
    float* out = (float*)d_out;

    cudaFuncSetAttribute(gemm1_kernel, cudaFuncAttributeMaxDynamicSharedMemorySize, DSMEM_BYTES);
    cudaFuncSetAttribute(gemm2_kernel, cudaFuncAttributeMaxDynamicSharedMemorySize, DSMEM_BYTES);

    reset_kernel<<<(ROWS_PAD + 255) / 256, 256>>>();
    router_kernel<<<N_TOK, 256>>>(x, gate);
    offsets_kernel<<<1, 32>>>();
    fill_kernel<<<(N_TOK + 255) / 256, 256>>>();
    zero_out_kernel<<<(out_size + 1023) / 1024, 1024>>>(out, out_size);
    gemm1_kernel<<<dim3(MAX_TILES, IDIM / 64), 256, DSMEM_BYTES>>>(x, fc1, fc2);
    gemm2_kernel<<<dim3(MAX_TILES, CDIM / 128), 256, DSMEM_BYTES>>>(proj, out);
}